// round 9
// baseline (speedup 1.0000x reference)
#include <cuda_runtime.h>
#include <cstdint>

#define IMG_H 1536
#define IMG_W 1536
#define NB    4
#define TO    28          // output tile edge
#define NT    55          // ceil(1536/28)

typedef unsigned long long ull;

// ---------------- f32x2 packed helpers (sm_103a) ----------------
__device__ __forceinline__ ull pk2(float lo, float hi) {
    ull r;
    asm("mov.b64 %0, {%1, %2};" : "=l"(r) : "f"(lo), "f"(hi));
    return r;
}
__device__ __forceinline__ void ffma2(ull& d, ull a, ull b) {
    asm("fma.rn.f32x2 %0, %1, %2, %0;" : "+l"(d) : "l"(a), "l"(b));
}
__device__ __forceinline__ void unpk2(ull v, float& lo, float& hi) {
    asm("mov.b64 {%0, %1}, %2;" : "=f"(lo), "=f"(hi) : "l"(v));
}

// Conv inner block. Co-pair packed accumulators:
//   acc[k][p][q] = packed (co=2q, co=2q+1) partial sums for output pixel
//                  (row = k ? r1 : r0, col = col + p),  k,p in {0,1}, q in 0..7.
// Weights in smem in PLAIN layout sw[(cin*9+t)*16 + co] (co contiguous):
//   one LDS.128 (ulonglong2) -> 4 weights (2 co-pairs) -> feeds 8 FFMA2.
// Input pixels duplicated into both packed lanes with one mov.b64 (alu pipe).
template<int CIN, int ISTR, int IPLANE>
__device__ __forceinline__ void conv_block(const float* __restrict__ sin,
                                           const float* __restrict__ sw,
                                           int col, int r0, int r1,
                                           ull acc[2][2][8]) {
#pragma unroll 1
    for (int cin = 0; cin < CIN; ++cin) {
        const float* base = sin + cin * IPLANE + col;
        ull dup[2][3][4];
#pragma unroll
        for (int k = 0; k < 2; ++k) {
            int r = k ? r1 : r0;
#pragma unroll
            for (int dy = 0; dy < 3; ++dy) {
                const float* p = base + (r + dy) * ISTR;
                float2 a = *(const float2*)p;         // cols col, col+1
                float2 b = *(const float2*)(p + 2);   // cols col+2, col+3
                dup[k][dy][0] = pk2(a.x, a.x);
                dup[k][dy][1] = pk2(a.y, a.y);
                dup[k][dy][2] = pk2(b.x, b.x);
                dup[k][dy][3] = pk2(b.y, b.y);
            }
        }
        const ulonglong2* w = (const ulonglong2*)sw + cin * 36;
#pragma unroll
        for (int t = 0; t < 9; ++t) {
            const int dy = t / 3, kx = t % 3;
#pragma unroll
            for (int j = 0; j < 4; ++j) {
                ulonglong2 wv = w[t * 4 + j];     // co 4j..4j+3
#pragma unroll
                for (int k = 0; k < 2; ++k) {
                    ffma2(acc[k][0][2 * j],     dup[k][dy][kx],     wv.x);
                    ffma2(acc[k][1][2 * j],     dup[k][dy][kx + 1], wv.x);
                    ffma2(acc[k][0][2 * j + 1], dup[k][dy][kx],     wv.y);
                    ffma2(acc[k][1][2 * j + 1], dup[k][dy][kx + 1], wv.y);
                }
            }
        }
    }
}

// Transpose one (co-pair, 2-col) acc pair into 2 col-pair words, mask, store.
__device__ __forceinline__ void mstore(float* p0, float* p1, ull aL, ull aR, ull mask) {
    float l0, l1, r0, r1;
    unpk2(aL, l0, l1);              // col L: co 2q, 2q+1
    unpk2(aR, r0, r1);              // col R: co 2q, 2q+1
    ull v0 = pk2(l0, r0);           // plane 2q   : (colL, colR)
    ull v1 = pk2(l1, r1);           // plane 2q+1 : (colL, colR)
    asm("mul.rn.f32x2 %0, %0, %1;" : "+l"(v0) : "l"(mask));
    asm("mul.rn.f32x2 %0, %0, %1;" : "+l"(v1) : "l"(mask));
    *(ull*)p0 = v0;
    *(ull*)p1 = v1;
}

// smem layout (floats):
//  s_h1 : 16*32*34 = 17408   conv1 out (halo 2), row stride 34
//  s_h2 : 16*30*32 = 15360   conv2 out (halo 1), row stride 32
//  s_in : 3*34*36  = 3672    input tile (halo 3), row stride 36
//  s_w1 : 432   s_w2 : 2304   s_w3 : 2304   (plain layout, co innermost)
// total = 41480 floats = 165920 bytes -> 1 CTA/SM
#define SMEM_BYTES 165920

__global__ __launch_bounds__(256, 1)
void net_fused_kernel(const float* __restrict__ x,
                      const float* __restrict__ w1,
                      const float* __restrict__ w2,
                      const float* __restrict__ w3,
                      float* __restrict__ out) {
    extern __shared__ float sm[];
    float* s_h1 = sm;                 // 17408
    float* s_h2 = s_h1 + 17408;       // 15360
    float* s_in = s_h2 + 15360;       // 3672
    float* s_w1 = s_in + 3672;        // 432
    float* s_w2 = s_w1 + 432;         // 2304
    float* s_w3 = s_w2 + 2304;        // 2304

    const int tid = threadIdx.x;
    const int tx = tid & 15;          // col pair 2*tx
    const int ty = tid >> 4;          // rows ty, ty+16
    const int ox = blockIdx.x * TO;
    const int oy = blockIdx.y * TO;
    const int bz = blockIdx.z;

    // ---- Stage A: input halo tile (3 x 34 x 34, zero-padded) + weights ----
    {
        const float* xb = x + (size_t)bz * 3 * IMG_H * IMG_W;
        for (int i = tid; i < 3 * 34 * 34; i += 256) {
            int cin = i / 1156;
            int rem = i - cin * 1156;
            int rr  = rem / 34;
            int cc  = rem - rr * 34;
            int gy = oy - 3 + rr;
            int gx = ox - 3 + cc;
            float v = 0.0f;
            if ((unsigned)gy < IMG_H && (unsigned)gx < IMG_W)
                v = xb[(size_t)cin * IMG_H * IMG_W + (size_t)gy * IMG_W + gx];
            s_in[cin * 1224 + rr * 36 + cc] = v;
        }
        // transpose weights: s_w[(cin*9+t)*16 + co] = w[co][cin*9+t]
        for (int i = tid; i < 432; i += 256)
            s_w1[i] = w1[(i & 15) * 27 + (i >> 4)];
        for (int i = tid; i < 2304; i += 256) {
            int co = i & 15, r = i >> 4;
            s_w2[i] = w2[co * 144 + r];
            s_w3[i] = w3[co * 144 + r];
        }
    }
    __syncthreads();

    // ---- Stage B: conv1 (3 -> 16) over 32x32 region -> s_h1 ----
    // Intermediates outside the image must be EXACT zero (the reference
    // zero-pads every conv layer) -> mask on store.
    {
        ull acc[2][2][8];
#pragma unroll
        for (int k = 0; k < 2; ++k)
#pragma unroll
            for (int p = 0; p < 2; ++p)
#pragma unroll
                for (int q = 0; q < 8; ++q) acc[k][p][q] = 0ULL;

        conv_block<3, 36, 1224>(s_in, s_w1, 2 * tx, ty, ty + 16, acc);

        int gx = ox - 2 + 2 * tx;
#pragma unroll
        for (int k = 0; k < 2; ++k) {
            int r = k ? (ty + 16) : ty;
            int gy = oy - 2 + r;
            float rowm = ((unsigned)gy < IMG_H) ? 1.0f : 0.0f;
            ull mask = pk2(((unsigned)gx < IMG_W) ? rowm : 0.0f,
                           ((unsigned)(gx + 1) < IMG_W) ? rowm : 0.0f);
            float* hp = s_h1 + r * 34 + 2 * tx;
#pragma unroll
            for (int q = 0; q < 8; ++q)
                mstore(hp + (2 * q) * 1088, hp + (2 * q + 1) * 1088,
                       acc[k][0][q], acc[k][1][q], mask);
        }
    }
    __syncthreads();

    // ---- Stage C: conv2 (16 -> 16) over 30x30 region -> s_h2 ----
    {
        ull acc[2][2][8];
#pragma unroll
        for (int k = 0; k < 2; ++k)
#pragma unroll
            for (int p = 0; p < 2; ++p)
#pragma unroll
                for (int q = 0; q < 8; ++q) acc[k][p][q] = 0ULL;

        int r1 = (ty < 14) ? (ty + 16) : 0;   // clamp loads for inactive row
        conv_block<16, 34, 1088>(s_h1, s_w2, 2 * tx, ty, r1, acc);

        if (tx < 15) {
            int gx = ox - 1 + 2 * tx;
#pragma unroll
            for (int k = 0; k < 2; ++k) {
                if (k && ty >= 14) break;
                int r = k ? (ty + 16) : ty;
                int gy = oy - 1 + r;
                float rowm = ((unsigned)gy < IMG_H) ? 1.0f : 0.0f;
                ull mask = pk2(((unsigned)gx < IMG_W) ? rowm : 0.0f,
                               ((unsigned)(gx + 1) < IMG_W) ? rowm : 0.0f);
                float* hp = s_h2 + r * 32 + 2 * tx;
#pragma unroll
                for (int q = 0; q < 8; ++q)
                    mstore(hp + (2 * q) * 960, hp + (2 * q + 1) * 960,
                           acc[k][0][q], acc[k][1][q], mask);
            }
        }
    }
    __syncthreads();

    // ---- Stage D: conv3 (16 -> 16) + ReLU over 28x28 -> global ----
    {
        ull acc[2][2][8];
#pragma unroll
        for (int k = 0; k < 2; ++k)
#pragma unroll
            for (int p = 0; p < 2; ++p)
#pragma unroll
                for (int q = 0; q < 8; ++q) acc[k][p][q] = 0ULL;

        int r1 = (ty < 12) ? (ty + 16) : 0;
        conv_block<16, 32, 960>(s_h2, s_w3, 2 * tx, ty, r1, acc);

        if (tx < 14) {
            int gx = ox + 2 * tx;
#pragma unroll
            for (int k = 0; k < 2; ++k) {
                if (k && ty >= 12) break;
                int r = k ? (ty + 16) : ty;
                int gy = oy + r;
                if (gy >= IMG_H || gx >= IMG_W) continue;   // gx even -> gx+1 ok
                float* ob = out + ((size_t)(bz * 16) * IMG_H + gy) * IMG_W + gx;
#pragma unroll
                for (int q = 0; q < 8; ++q) {
                    float l0, l1, r0, r1v;
                    unpk2(acc[k][0][q], l0, l1);
                    unpk2(acc[k][1][q], r0, r1v);
                    float2 v0 = make_float2(fmaxf(l0, 0.0f), fmaxf(r0, 0.0f));
                    float2 v1 = make_float2(fmaxf(l1, 0.0f), fmaxf(r1v, 0.0f));
                    *(float2*)(ob + (size_t)(2 * q) * IMG_H * IMG_W)     = v0;
                    *(float2*)(ob + (size_t)(2 * q + 1) * IMG_H * IMG_W) = v1;
                }
            }
        }
    }
}

extern "C" void kernel_launch(void* const* d_in, const int* in_sizes, int n_in,
                              void* d_out, int out_size) {
    const float* x  = (const float*)d_in[0];
    const float* w1 = (const float*)d_in[1];
    const float* w2 = (const float*)d_in[2];
    const float* w3 = (const float*)d_in[3];
    float* out = (float*)d_out;

    cudaFuncSetAttribute(net_fused_kernel,
                         cudaFuncAttributeMaxDynamicSharedMemorySize, SMEM_BYTES);

    dim3 grid(NT, NT, NB);
    net_fused_kernel<<<grid, 256, SMEM_BYTES>>>(x, w1, w2, w3, out);
}

// round 11
// speedup vs baseline: 1.9838x; 1.9838x over previous
#include <cuda_runtime.h>
#include <cuda_fp16.h>
#include <cstdint>

#define IMG   1536
#define NB    4
#define TOUT  24
#define NT    64          // 1536/24

typedef unsigned long long ull;

// ---- byte offsets in dynamic smem ----
// hh/hl: 864 padded pixel rows * 32 B (16 f16 ch) each, half-swizzled
#define OFF_HH   0
#define OFF_HL   27648
#define OFF_W2H  55296    // 9 taps * 16 n * 16 k f16 = 4608 B each
#define OFF_W2L  59904
#define OFF_W3H  64512
#define OFF_W3L  69120
#define OFF_W1   73728    // 432 f32
#define OFF_IN   75456    // 3 * 30 * 32 f32 = 11520 B
#define SMEM_BYTES 86976

// ---------------- helpers ----------------
__device__ __forceinline__ ull pk2(float lo, float hi) {
    ull r; asm("mov.b64 %0, {%1, %2};" : "=l"(r) : "f"(lo), "f"(hi)); return r;
}
__device__ __forceinline__ void ffma2(ull& d, ull a, ull b) {
    asm("fma.rn.f32x2 %0, %1, %2, %0;" : "+l"(d) : "l"(a), "l"(b));
}
__device__ __forceinline__ void unpk2(ull v, float& lo, float& hi) {
    asm("mov.b64 {%0, %1}, %2;" : "=f"(lo), "=f"(hi) : "l"(v));
}
__device__ __forceinline__ uint32_t smem_u32(const void* p) {
    uint32_t a;
    asm("{ .reg .u64 t; cvta.to.shared.u64 t, %1; cvt.u32.u64 %0, t; }" : "=r"(a) : "l"(p));
    return a;
}
__device__ __forceinline__ uint32_t packh2(__half a, __half b) {
    __half2 t = __halves2half2(a, b);
    return *reinterpret_cast<uint32_t*>(&t);
}

#define LDSM4(R, ADDR) \
    asm volatile("ldmatrix.sync.aligned.m8n8.x4.shared.b16 {%0,%1,%2,%3}, [%4];" \
        : "=r"((R)[0]), "=r"((R)[1]), "=r"((R)[2]), "=r"((R)[3]) : "r"(ADDR))

#define MMA16816(D, A, B0, B1) \
    asm volatile("mma.sync.aligned.m16n8k16.row.col.f32.f16.f16.f32 " \
        "{%0,%1,%2,%3}, {%4,%5,%6,%7}, {%8,%9}, {%0,%1,%2,%3};" \
        : "+f"((D)[0]), "+f"((D)[1]), "+f"((D)[2]), "+f"((D)[3]) \
        : "r"((A)[0]), "r"((A)[1]), "r"((A)[2]), "r"((A)[3]), "r"(B0), "r"(B1))

// One conv layer as implicit GEMM over the 784-pixel buffer.
// A rows = pixels (hi/lo f16), B = per-tap 16x16 weight blocks (hi/lo f16).
// 3xFP16 split: D += Ah*Bh + Ah*Bl + Al*Bh  (fp32 accumulate).
template<bool FINAL>
__device__ __forceinline__ void mma_layer(char* smc, int lane, int wid,
                                          int whOff, int wlOff,
                                          int ox, int oy, int bz,
                                          float* __restrict__ out) {
    const uint32_t a_hh = smem_u32(smc + OFF_HH);
    const uint32_t* whw = (const uint32_t*)(smc + whOff);
    const uint32_t* wlw = (const uint32_t*)(smc + wlOff);
    const int l15 = lane & 15;
    const int hsel = lane >> 4;            // which 16B half (k 0-7 / 8-15)
    const int kq = lane & 3;
    const int nr = (lane >> 2) & 7;

    float d[7][2][4];
#pragma unroll
    for (int i = 0; i < 7; ++i)
#pragma unroll
        for (int nh = 0; nh < 2; ++nh)
#pragma unroll
            for (int j = 0; j < 4; ++j) d[i][nh][j] = 0.0f;

#pragma unroll 1
    for (int tap = 0; tap < 9; ++tap) {
        const int shift = (tap / 3 - 1) * 28 + (tap % 3) - 1;
        uint32_t bh[2][2], bl[2][2];
#pragma unroll
        for (int nh = 0; nh < 2; ++nh) {
            int wi = tap * 128 + (nr + nh * 8) * 8 + kq;
            bh[nh][0] = whw[wi];     bh[nh][1] = whw[wi + 4];
            bl[nh][0] = wlw[wi];     bl[nh][1] = wlw[wi + 4];
        }
#pragma unroll
        for (int i = 0; i < 7; ++i) {
            int b = wid + 8 * i;
            if (b < 49) {
                int p = b * 16 + 32 + shift + l15;      // padded pixel index
                uint32_t addr = a_hh + p * 32 + ((hsel ^ ((p >> 2) & 1)) << 4);
                uint32_t A[4], AL[4];
                LDSM4(A, addr);
                LDSM4(AL, addr + (OFF_HL - OFF_HH));
                MMA16816(d[i][0], A,  bh[0][0], bh[0][1]);
                MMA16816(d[i][1], A,  bh[1][0], bh[1][1]);
                MMA16816(d[i][0], A,  bl[0][0], bl[0][1]);
                MMA16816(d[i][1], A,  bl[1][0], bl[1][1]);
                MMA16816(d[i][0], AL, bh[0][0], bh[0][1]);
                MMA16816(d[i][1], AL, bh[1][0], bh[1][1]);
            }
        }
    }

    if (!FINAL) __syncthreads();   // all ldmatrix reads done before overwrite

    const int c0 = 2 * (lane & 3);
#pragma unroll
    for (int i = 0; i < 7; ++i) {
        int b = wid + 8 * i;
        if (b >= 49) continue;
#pragma unroll
        for (int px = 0; px < 2; ++px) {
            int p = b * 16 + (lane >> 2) + px * 8;   // buffer pixel 0..783
            int rr = p / 28, cc = p - rr * 28;
            float v0 = d[i][0][2 * px], v1 = d[i][0][2 * px + 1];
            float v8 = d[i][1][2 * px], v9 = d[i][1][2 * px + 1];
            if (FINAL) {
                if (rr >= 2 && rr < 26 && cc >= 2 && cc < 26) {
                    int gy = oy + rr - 2, gx = ox + cc - 2;
                    float* ob = out + ((size_t)(bz * 16) * IMG + gy) * IMG + gx;
                    ob[(size_t)(c0)     * IMG * IMG] = fmaxf(v0, 0.0f);
                    ob[(size_t)(c0 + 1) * IMG * IMG] = fmaxf(v1, 0.0f);
                    ob[(size_t)(c0 + 8) * IMG * IMG] = fmaxf(v8, 0.0f);
                    ob[(size_t)(c0 + 9) * IMG * IMG] = fmaxf(v9, 0.0f);
                }
            } else {
                // per-layer SAME padding: zero outside image
                float mval = (((unsigned)(oy + rr - 2) < IMG) &&
                              ((unsigned)(ox + cc - 2) < IMG)) ? 1.0f : 0.0f;
                v0 *= mval; v1 *= mval; v8 *= mval; v9 *= mval;
                __half h0 = __float2half_rn(v0), h1 = __float2half_rn(v1);
                __half h8 = __float2half_rn(v8), h9 = __float2half_rn(v9);
                __half e0 = __float2half_rn(v0 - __half2float(h0));
                __half e1 = __float2half_rn(v1 - __half2float(h1));
                __half e8 = __float2half_rn(v8 - __half2float(h8));
                __half e9 = __float2half_rn(v9 - __half2float(h9));
                int pp = p + 32;
                int s = (pp >> 2) & 1;
                char* rb = smc + OFF_HH + pp * 32;
                *(uint32_t*)(rb + (s << 4)       + c0 * 2) = packh2(h0, h1);
                *(uint32_t*)(rb + ((1 ^ s) << 4) + c0 * 2) = packh2(h8, h9);
                rb += (OFF_HL - OFF_HH);
                *(uint32_t*)(rb + (s << 4)       + c0 * 2) = packh2(e0, e1);
                *(uint32_t*)(rb + ((1 ^ s) << 4) + c0 * 2) = packh2(e8, e9);
            }
        }
    }
}

__global__ __launch_bounds__(256, 2)
void net_fused_kernel(const float* __restrict__ x,
                      const float* __restrict__ w1,
                      const float* __restrict__ w2,
                      const float* __restrict__ w3,
                      float* __restrict__ out) {
    extern __shared__ char smc[];
    const int tid  = threadIdx.x;
    const int lane = tid & 31;
    const int wid  = tid >> 5;
    const int ox = blockIdx.x * TOUT;
    const int oy = blockIdx.y * TOUT;
    const int bz = blockIdx.z;

    float*  s_in = (float*)(smc + OFF_IN);
    float*  s_w1 = (float*)(smc + OFF_W1);
    __half* w2h  = (__half*)(smc + OFF_W2H);
    __half* w2l  = (__half*)(smc + OFF_W2L);
    __half* w3h  = (__half*)(smc + OFF_W3H);
    __half* w3l  = (__half*)(smc + OFF_W3L);

    // ---- Stage A: input halo (3 x 30 x 30, stride 32) + weights + pads ----
    {
        const float* xb = x + (size_t)bz * 3 * IMG * IMG;
        for (int i = tid; i < 3 * 30 * 30; i += 256) {
            int cin = i / 900;
            int rem = i - cin * 900;
            int rr = rem / 30, cc = rem - rr * 30;
            int gy = oy - 3 + rr, gx = ox - 3 + cc;
            float v = 0.0f;
            if ((unsigned)gy < IMG && (unsigned)gx < IMG)
                v = xb[(size_t)cin * IMG * IMG + (size_t)gy * IMG + gx];
            s_in[cin * 960 + rr * 32 + cc] = v;
        }
        for (int i = tid; i < 432; i += 256)
            s_w1[i] = w1[(i & 15) * 27 + (i >> 4)];
        // conv2/3 weights: [tap][n=co 16][k=ci 16], fp16 hi/lo split
        for (int i = tid; i < 2304; i += 256) {
            int tap = i >> 8, n = (i >> 4) & 15, k = i & 15;
            float v2 = w2[n * 144 + k * 9 + tap];
            float v3 = w3[n * 144 + k * 9 + tap];
            __half a2 = __float2half_rn(v2);
            __half a3 = __float2half_rn(v3);
            w2h[i] = a2;  w2l[i] = __float2half_rn(v2 - __half2float(a2));
            w3h[i] = a3;  w3l[i] = __float2half_rn(v3 - __half2float(a3));
        }
        // zero pad pixel rows: padded idx 0..31 and 816..863
        for (int p = tid; p < 80; p += 256) {
            int pp = (p < 32) ? p : (784 + p);   // 816..863
            *(uint4*)(smc + OFF_HH + pp * 32)      = make_uint4(0, 0, 0, 0);
            *(uint4*)(smc + OFF_HH + pp * 32 + 16) = make_uint4(0, 0, 0, 0);
            *(uint4*)(smc + OFF_HL + pp * 32)      = make_uint4(0, 0, 0, 0);
            *(uint4*)(smc + OFF_HL + pp * 32 + 16) = make_uint4(0, 0, 0, 0);
        }
    }
    __syncthreads();

    // ---- Stage B: conv1 (3->16) FFMA2 over 28x28 buffer, split f16 store ----
#pragma unroll 1
    for (int m = tid; m < 784; m += 256) {
        int rr = m / 28, cc = m - rr * 28;
        ull acc[8];
#pragma unroll
        for (int q = 0; q < 8; ++q) acc[q] = 0ULL;
#pragma unroll
        for (int cin = 0; cin < 3; ++cin) {
            const float* bp = s_in + cin * 960 + rr * 32 + cc;
            float a[9];
#pragma unroll
            for (int dy = 0; dy < 3; ++dy) {
                a[dy * 3 + 0] = bp[dy * 32 + 0];
                a[dy * 3 + 1] = bp[dy * 32 + 1];
                a[dy * 3 + 2] = bp[dy * 32 + 2];
            }
            const ulonglong2* w = (const ulonglong2*)s_w1 + cin * 36;
#pragma unroll
            for (int t = 0; t < 9; ++t) {
                ull dup = pk2(a[t], a[t]);
#pragma unroll
                for (int j = 0; j < 4; ++j) {
                    ulonglong2 wv = w[t * 4 + j];
                    ffma2(acc[2 * j],     dup, wv.x);
                    ffma2(acc[2 * j + 1], dup, wv.y);
                }
            }
        }
        float mval = (((unsigned)(oy + rr - 2) < IMG) &&
                      ((unsigned)(ox + cc - 2) < IMG)) ? 1.0f : 0.0f;
        float v[16];
#pragma unroll
        for (int q = 0; q < 8; ++q) {
            unpk2(acc[q], v[2 * q], v[2 * q + 1]);
            v[2 * q] *= mval; v[2 * q + 1] *= mval;
        }
        uint32_t hi[8], lo[8];
#pragma unroll
        for (int j = 0; j < 8; ++j) {
            __half a0 = __float2half_rn(v[2 * j]);
            __half a1 = __float2half_rn(v[2 * j + 1]);
            __half e0 = __float2half_rn(v[2 * j]     - __half2float(a0));
            __half e1 = __float2half_rn(v[2 * j + 1] - __half2float(a1));
            hi[j] = packh2(a0, a1);
            lo[j] = packh2(e0, e1);
        }
        int pp = m + 32;
        int s = (pp >> 2) & 1;
        char* rb = smc + OFF_HH + pp * 32;
        *(uint4*)(rb + (s << 4))       = make_uint4(hi[0], hi[1], hi[2], hi[3]);
        *(uint4*)(rb + ((1 ^ s) << 4)) = make_uint4(hi[4], hi[5], hi[6], hi[7]);
        rb += (OFF_HL - OFF_HH);
        *(uint4*)(rb + (s << 4))       = make_uint4(lo[0], lo[1], lo[2], lo[3]);
        *(uint4*)(rb + ((1 ^ s) << 4)) = make_uint4(lo[4], lo[5], lo[6], lo[7]);
    }
    __syncthreads();

    // ---- Stage C: conv2 via mma.sync (writes h buffers back) ----
    mma_layer<false>(smc, lane, wid, OFF_W2H, OFF_W2L, ox, oy, bz, out);
    __syncthreads();

    // ---- Stage D: conv3 via mma.sync + ReLU -> global ----
    mma_layer<true>(smc, lane, wid, OFF_W3H, OFF_W3L, ox, oy, bz, out);
}

extern "C" void kernel_launch(void* const* d_in, const int* in_sizes, int n_in,
                              void* d_out, int out_size) {
    const float* x  = (const float*)d_in[0];
    const float* w1 = (const float*)d_in[1];
    const float* w2 = (const float*)d_in[2];
    const float* w3 = (const float*)d_in[3];
    float* out = (float*)d_out;

    cudaFuncSetAttribute(net_fused_kernel,
                         cudaFuncAttributeMaxDynamicSharedMemorySize, SMEM_BYTES);

    dim3 grid(NT, NT, NB);
    net_fused_kernel<<<grid, 256, SMEM_BYTES>>>(x, w1, w2, w3, out);
}

// round 13
// speedup vs baseline: 2.1485x; 1.0830x over previous
#include <cuda_runtime.h>
#include <cuda_fp16.h>
#include <cstdint>

#define IMG   1536
#define NB    4
#define TOX   28          // output tile width  (buffer 32 cols)
#define TOY   20          // output tile height (buffer 24 rows)
#define NTX   55
#define NTY   77
#define NTHR  384

typedef unsigned long long ull;

// ---- byte offsets in dynamic smem ----
// hh/hl: 848 padded pixel rows (40 pad + 768 + 40 pad) * 32 B (16 f16 ch)
#define OFF_HH   0
#define OFF_HL   27136
#define OFF_W2H  54272    // 9 taps * 128 half2-words * 4 B = 4608 B each
#define OFF_W2L  58880
#define OFF_W3H  63488
#define OFF_W3L  68096
#define OFF_W1   72704    // 432 f32
#define OFF_IN   74432    // 3 * 26 * 36 f32 = 11232 B
#define SMEM_BYTES 85664

// ---------------- helpers ----------------
__device__ __forceinline__ ull pk2(float lo, float hi) {
    ull r; asm("mov.b64 %0, {%1, %2};" : "=l"(r) : "f"(lo), "f"(hi)); return r;
}
__device__ __forceinline__ void ffma2(ull& d, ull a, ull b) {
    asm("fma.rn.f32x2 %0, %1, %2, %0;" : "+l"(d) : "l"(a), "l"(b));
}
__device__ __forceinline__ void unpk2(ull v, float& lo, float& hi) {
    asm("mov.b64 {%0, %1}, %2;" : "=f"(lo), "=f"(hi) : "l"(v));
}
__device__ __forceinline__ uint32_t smem_u32(const void* p) {
    uint32_t a;
    asm("{ .reg .u64 t; cvta.to.shared.u64 t, %1; cvt.u32.u64 %0, t; }" : "=r"(a) : "l"(p));
    return a;
}
__device__ __forceinline__ uint32_t packh2(__half a, __half b) {
    __half2 t = __halves2half2(a, b);
    return *reinterpret_cast<uint32_t*>(&t);
}

#define LDSM4(R, ADDR) \
    asm volatile("ldmatrix.sync.aligned.m8n8.x4.shared.b16 {%0,%1,%2,%3}, [%4];" \
        : "=r"((R)[0]), "=r"((R)[1]), "=r"((R)[2]), "=r"((R)[3]) : "r"(ADDR))

#define MMA16816(D, A, B0, B1) \
    asm volatile("mma.sync.aligned.m16n8k16.row.col.f32.f16.f16.f32 " \
        "{%0,%1,%2,%3}, {%4,%5,%6,%7}, {%8,%9}, {%0,%1,%2,%3};" \
        : "+f"((D)[0]), "+f"((D)[1]), "+f"((D)[2]), "+f"((D)[3]) \
        : "r"((A)[0]), "r"((A)[1]), "r"((A)[2]), "r"((A)[3]), "r"(B0), "r"(B1))

// One conv layer as implicit GEMM over the 768-pixel buffer (48 M-blocks,
// 4 per warp, 12 warps). 3xFP16 split: D += Ah*Bh + Ah*Bl + Al*Bh.
template<bool FINAL>
__device__ __forceinline__ void mma_layer(char* smc, int lane, int wid,
                                          int whOff, int wlOff,
                                          int ox, int oy, int bz,
                                          float* __restrict__ out) {
    const uint32_t a_hh = smem_u32(smc + OFF_HH);
    const uint32_t* whw = (const uint32_t*)(smc + whOff);
    const uint32_t* wlw = (const uint32_t*)(smc + wlOff);
    const int l15 = lane & 15;
    const int hsel = lane >> 4;            // which 16B half (ch 0-7 / 8-15)

    float d[4][2][4];
#pragma unroll
    for (int i = 0; i < 4; ++i)
#pragma unroll
        for (int nh = 0; nh < 2; ++nh)
#pragma unroll
            for (int j = 0; j < 4; ++j) d[i][nh][j] = 0.0f;

#pragma unroll 1
    for (int tap = 0; tap < 9; ++tap) {
        const int shift = (tap / 3 - 1) * 32 + (tap % 3) - 1;
        // B fragments, fragment-order layout -> conflict-free 1-wf LDS.32
        uint32_t bh[2][2], bl[2][2];
#pragma unroll
        for (int nh = 0; nh < 2; ++nh)
#pragma unroll
            for (int r = 0; r < 2; ++r) {
                int wi = tap * 128 + r * 64 + nh * 32 + lane;
                bh[nh][r] = whw[wi];
                bl[nh][r] = wlw[wi];
            }
#pragma unroll
        for (int i = 0; i < 4; ++i) {
            int b = wid + 12 * i;
            int p = b * 16 + 40 + shift + l15;      // padded pixel index
            uint32_t addr = a_hh + p * 32 + ((hsel ^ ((p >> 2) & 1)) << 4);
            uint32_t A[4], AL[4];
            LDSM4(A, addr);
            LDSM4(AL, addr + (OFF_HL - OFF_HH));
            MMA16816(d[i][0], A,  bh[0][0], bh[0][1]);
            MMA16816(d[i][1], A,  bh[1][0], bh[1][1]);
            MMA16816(d[i][0], A,  bl[0][0], bl[0][1]);
            MMA16816(d[i][1], A,  bl[1][0], bl[1][1]);
            MMA16816(d[i][0], AL, bh[0][0], bh[0][1]);
            MMA16816(d[i][1], AL, bh[1][0], bh[1][1]);
        }
    }

    if (!FINAL) __syncthreads();   // all ldmatrix reads done before overwrite

    const int c0 = 2 * (lane & 3);
#pragma unroll
    for (int i = 0; i < 4; ++i) {
        int b = wid + 12 * i;
#pragma unroll
        for (int px = 0; px < 2; ++px) {
            int p = b * 16 + (lane >> 2) + px * 8;   // buffer pixel 0..767
            int rr = p >> 5, cc = p & 31;
            float v0 = d[i][0][2 * px], v1 = d[i][0][2 * px + 1];
            float v8 = d[i][1][2 * px], v9 = d[i][1][2 * px + 1];
            if (FINAL) {
                int gy = oy + rr - 2, gx = ox + cc - 2;
                if (rr >= 2 && rr < 22 && cc >= 2 && cc < 30 &&
                    gy < IMG && gx < IMG) {
                    float* ob = out + ((size_t)(bz * 16) * IMG + gy) * IMG + gx;
                    ob[(size_t)(c0)     * IMG * IMG] = fmaxf(v0, 0.0f);
                    ob[(size_t)(c0 + 1) * IMG * IMG] = fmaxf(v1, 0.0f);
                    ob[(size_t)(c0 + 8) * IMG * IMG] = fmaxf(v8, 0.0f);
                    ob[(size_t)(c0 + 9) * IMG * IMG] = fmaxf(v9, 0.0f);
                }
            } else {
                // per-layer SAME padding: zero outside image
                float mval = (((unsigned)(oy + rr - 2) < IMG) &&
                              (((unsigned)(ox + cc - 2)) < IMG)) ? 1.0f : 0.0f;
                v0 *= mval; v1 *= mval; v8 *= mval; v9 *= mval;
                __half h0 = __float2half_rn(v0), h1 = __float2half_rn(v1);
                __half h8 = __float2half_rn(v8), h9 = __float2half_rn(v9);
                __half e0 = __float2half_rn(v0 - __half2float(h0));
                __half e1 = __float2half_rn(v1 - __half2float(h1));
                __half e8 = __float2half_rn(v8 - __half2float(h8));
                __half e9 = __float2half_rn(v9 - __half2float(h9));
                int pp = p + 40;
                int s = (pp >> 2) & 1;
                char* rb = smc + OFF_HH + pp * 32;
                *(uint32_t*)(rb + (s << 4)       + c0 * 2) = packh2(h0, h1);
                *(uint32_t*)(rb + ((1 ^ s) << 4) + c0 * 2) = packh2(h8, h9);
                rb += (OFF_HL - OFF_HH);
                *(uint32_t*)(rb + (s << 4)       + c0 * 2) = packh2(e0, e1);
                *(uint32_t*)(rb + ((1 ^ s) << 4) + c0 * 2) = packh2(e8, e9);
            }
        }
    }
}

__global__ __launch_bounds__(NTHR, 2)
void net_fused_kernel(const float* __restrict__ x,
                      const float* __restrict__ w1,
                      const float* __restrict__ w2,
                      const float* __restrict__ w3,
                      float* __restrict__ out) {
    extern __shared__ char smc[];
    const int tid  = threadIdx.x;
    const int lane = tid & 31;
    const int wid  = tid >> 5;
    const int ox = blockIdx.x * TOX;
    const int oy = blockIdx.y * TOY;
    const int bz = blockIdx.z;

    float*  s_in = (float*)(smc + OFF_IN);
    float*  s_w1 = (float*)(smc + OFF_W1);
    __half* w2h  = (__half*)(smc + OFF_W2H);
    __half* w2l  = (__half*)(smc + OFF_W2L);
    __half* w3h  = (__half*)(smc + OFF_W3H);
    __half* w3l  = (__half*)(smc + OFF_W3L);

    // ---- Stage A: input halo (3 x 26 x 34, stride 36) + weights + pads ----
    {
        const float* xb = x + (size_t)bz * 3 * IMG * IMG;
        for (int i = tid; i < 3 * 26 * 34; i += NTHR) {
            int cin = i / 884;
            int rem = i - cin * 884;
            int rr = rem / 34, cc = rem - rr * 34;
            int gy = oy - 3 + rr, gx = ox - 3 + cc;
            float v = 0.0f;
            if ((unsigned)gy < IMG && (unsigned)gx < IMG)
                v = xb[(size_t)cin * IMG * IMG + (size_t)gy * IMG + gx];
            s_in[cin * 936 + rr * 36 + cc] = v;
        }
        for (int i = tid; i < 432; i += NTHR)
            s_w1[i] = w1[(i & 15) * 27 + (i >> 4)];
        // conv2/3 weights in fragment order: half2 word (tap, n, k2) at
        //   tap*128 + (k2>>2)*64 + (n>>3)*32 + (n&7)*4 + (k2&3)
        for (int i = tid; i < 2304; i += NTHR) {
            int tap = i >> 8, n = (i >> 4) & 15, k = i & 15;
            int k2 = k >> 1;
            int widx = tap * 128 + (k2 >> 2) * 64 + ((n >> 3) << 5)
                     + ((n & 7) << 2) + (k2 & 3);
            int hidx = widx * 2 + (k & 1);
            float v2 = w2[n * 144 + k * 9 + tap];
            float v3 = w3[n * 144 + k * 9 + tap];
            __half a2 = __float2half_rn(v2);
            __half a3 = __float2half_rn(v3);
            w2h[hidx] = a2;  w2l[hidx] = __float2half_rn(v2 - __half2float(a2));
            w3h[hidx] = a3;  w3l[hidx] = __float2half_rn(v3 - __half2float(a3));
        }
        // zero pad pixel rows: padded idx 0..39 and 808..847
        for (int p = tid; p < 80; p += NTHR) {
            int pp = (p < 40) ? p : (768 + p);   // 808..847
            *(uint4*)(smc + OFF_HH + pp * 32)      = make_uint4(0, 0, 0, 0);
            *(uint4*)(smc + OFF_HH + pp * 32 + 16) = make_uint4(0, 0, 0, 0);
            *(uint4*)(smc + OFF_HL + pp * 32)      = make_uint4(0, 0, 0, 0);
            *(uint4*)(smc + OFF_HL + pp * 32 + 16) = make_uint4(0, 0, 0, 0);
        }
    }
    __syncthreads();

    // ---- Stage B: conv1 (3->16) FFMA2 over 24x32 buffer, split f16 store ----
#pragma unroll 1
    for (int m = tid; m < 768; m += NTHR) {
        int rr = m >> 5, cc = m & 31;
        ull acc[8];
#pragma unroll
        for (int q = 0; q < 8; ++q) acc[q] = 0ULL;
#pragma unroll
        for (int cin = 0; cin < 3; ++cin) {
            const float* bp = s_in + cin * 936 + rr * 36 + cc;
            float a[9];
#pragma unroll
            for (int dy = 0; dy < 3; ++dy) {
                a[dy * 3 + 0] = bp[dy * 36 + 0];
                a[dy * 3 + 1] = bp[dy * 36 + 1];
                a[dy * 3 + 2] = bp[dy * 36 + 2];
            }
            const ulonglong2* w = (const ulonglong2*)s_w1 + cin * 36;
#pragma unroll
            for (int t = 0; t < 9; ++t) {
                ull dup = pk2(a[t], a[t]);
#pragma unroll
                for (int j = 0; j < 4; ++j) {
                    ulonglong2 wv = w[t * 4 + j];
                    ffma2(acc[2 * j],     dup, wv.x);
                    ffma2(acc[2 * j + 1], dup, wv.y);
                }
            }
        }
        float mval = (((unsigned)(oy + rr - 2) < IMG) &&
                      (((unsigned)(ox + cc - 2)) < IMG)) ? 1.0f : 0.0f;
        float v[16];
#pragma unroll
        for (int q = 0; q < 8; ++q) {
            unpk2(acc[q], v[2 * q], v[2 * q + 1]);
            v[2 * q] *= mval; v[2 * q + 1] *= mval;
        }
        uint32_t hi[8], lo[8];
#pragma unroll
        for (int j = 0; j < 8; ++j) {
            __half a0 = __float2half_rn(v[2 * j]);
            __half a1 = __float2half_rn(v[2 * j + 1]);
            __half e0 = __float2half_rn(v[2 * j]     - __half2float(a0));
            __half e1 = __float2half_rn(v[2 * j + 1] - __half2float(a1));
            hi[j] = packh2(a0, a1);
            lo[j] = packh2(e0, e1);
        }
        int pp = m + 40;
        int s = (pp >> 2) & 1;
        char* rb = smc + OFF_HH + pp * 32;
        *(uint4*)(rb + (s << 4))       = make_uint4(hi[0], hi[1], hi[2], hi[3]);
        *(uint4*)(rb + ((1 ^ s) << 4)) = make_uint4(hi[4], hi[5], hi[6], hi[7]);
        rb += (OFF_HL - OFF_HH);
        *(uint4*)(rb + (s << 4))       = make_uint4(lo[0], lo[1], lo[2], lo[3]);
        *(uint4*)(rb + ((1 ^ s) << 4)) = make_uint4(lo[4], lo[5], lo[6], lo[7]);
    }
    __syncthreads();

    // ---- Stage C: conv2 via mma.sync (writes h buffers back) ----
    mma_layer<false>(smc, lane, wid, OFF_W2H, OFF_W2L, ox, oy, bz, out);
    __syncthreads();

    // ---- Stage D: conv3 via mma.sync + ReLU -> global ----
    mma_layer<true>(smc, lane, wid, OFF_W3H, OFF_W3L, ox, oy, bz, out);
}

extern "C" void kernel_launch(void* const* d_in, const int* in_sizes, int n_in,
                              void* d_out, int out_size) {
    const float* x  = (const float*)d_in[0];
    const float* w1 = (const float*)d_in[1];
    const float* w2 = (const float*)d_in[2];
    const float* w3 = (const float*)d_in[3];
    float* out = (float*)d_out;

    cudaFuncSetAttribute(net_fused_kernel,
                         cudaFuncAttributeMaxDynamicSharedMemorySize, SMEM_BYTES);

    dim3 grid(NTX, NTY, NB);
    net_fused_kernel<<<grid, NTHR, SMEM_BYTES>>>(x, w1, w2, w3, out);
}

// round 14
// speedup vs baseline: 2.3403x; 1.0893x over previous
#include <cuda_runtime.h>
#include <cuda_fp16.h>
#include <cstdint>

#define IMG   1536
#define NB    4
#define TOX   28          // output tile width  (buffer 32 cols)
#define TOY   20          // output tile height (buffer 24 rows)
#define NTX   55
#define NTY   77
#define NTHR  384

typedef unsigned long long ull;

// ---- byte offsets in dynamic smem ----
// hh/hl: 848 padded pixel rows (40 pad + 768 + 40 pad) * 32 B (16 f16 ch)
#define OFF_HH   0
#define OFF_HL   27136
#define OFF_W2H  54272    // 9 taps * 32 lanes * 16 B = 4608 B each
#define OFF_W2L  58880
#define OFF_W3H  63488
#define OFF_W3L  68096
#define OFF_W1   72704    // 432 f32
#define OFF_IN   74432    // 3 * 26 * 36 f32 = 11232 B
#define SMEM_BYTES 85664

// ---------------- helpers ----------------
__device__ __forceinline__ ull pk2(float lo, float hi) {
    ull r; asm("mov.b64 %0, {%1, %2};" : "=l"(r) : "f"(lo), "f"(hi)); return r;
}
__device__ __forceinline__ void ffma2(ull& d, ull a, ull b) {
    asm("fma.rn.f32x2 %0, %1, %2, %0;" : "+l"(d) : "l"(a), "l"(b));
}
__device__ __forceinline__ void unpk2(ull v, float& lo, float& hi) {
    asm("mov.b64 {%0, %1}, %2;" : "=f"(lo), "=f"(hi) : "l"(v));
}
__device__ __forceinline__ uint32_t smem_u32(const void* p) {
    uint32_t a;
    asm("{ .reg .u64 t; cvta.to.shared.u64 t, %1; cvt.u32.u64 %0, t; }" : "=r"(a) : "l"(p));
    return a;
}
__device__ __forceinline__ uint32_t packh2(__half a, __half b) {
    __half2 t = __halves2half2(a, b);
    return *reinterpret_cast<uint32_t*>(&t);
}

#define LDSM4(R, ADDR) \
    asm volatile("ldmatrix.sync.aligned.m8n8.x4.shared.b16 {%0,%1,%2,%3}, [%4];" \
        : "=r"((R)[0]), "=r"((R)[1]), "=r"((R)[2]), "=r"((R)[3]) : "r"(ADDR))

#define MMA16816(D, A, B0, B1) \
    asm volatile("mma.sync.aligned.m16n8k16.row.col.f32.f16.f16.f32 " \
        "{%0,%1,%2,%3}, {%4,%5,%6,%7}, {%8,%9}, {%0,%1,%2,%3};" \
        : "+f"((D)[0]), "+f"((D)[1]), "+f"((D)[2]), "+f"((D)[3]) \
        : "r"((A)[0]), "r"((A)[1]), "r"((A)[2]), "r"((A)[3]), "r"(B0), "r"(B1))

// 3xFP16 split terms for one (block, tap): D += Ah*Bh + Ah*Bl + Al*Bh
#define DO6(DACC, A, AL, BH, BL) \
    MMA16816((DACC)[0], A,  (BH)[0][0], (BH)[0][1]); \
    MMA16816((DACC)[1], A,  (BH)[1][0], (BH)[1][1]); \
    MMA16816((DACC)[0], A,  (BL)[0][0], (BL)[0][1]); \
    MMA16816((DACC)[1], A,  (BL)[1][0], (BL)[1][1]); \
    MMA16816((DACC)[0], AL, (BH)[0][0], (BH)[0][1]); \
    MMA16816((DACC)[1], AL, (BH)[1][0], (BH)[1][1]);

// One conv layer as implicit GEMM over the 768-pixel buffer.
// Each warp owns 4 CONSECUTIVE M-blocks (b = 4*wid .. 4*wid+3, 16 px each).
// Since the buffer row = 32 px = 2 blocks, tap (dy,dx) of block b reads the
// same A fragment as tap (0,dx) of block b+2dy: fragment id f = b + 2*dy.
// Stream f = -2..5 per dx: load each hi/lo fragment ONCE, feed up to 3 blocks.
// A-ldmatrix count: 48 per warp-layer instead of 72 (-33% A traffic).
template<bool FINAL>
__device__ __forceinline__ void mma_layer(char* smc, int lane, int wid,
                                          int whOff, int wlOff,
                                          int ox, int oy, int bz,
                                          float* __restrict__ out) {
    const uint32_t a_hh = smem_u32(smc + OFF_HH);
    const uint4* whq = (const uint4*)(smc + whOff);
    const uint4* wlq = (const uint4*)(smc + wlOff);
    const int l15 = lane & 15;
    const int hsel = lane >> 4;            // which 16B half (ch 0-7 / 8-15)
    const int base_blk = wid * 4;

    float d[4][2][4];
#pragma unroll
    for (int i = 0; i < 4; ++i)
#pragma unroll
        for (int nh = 0; nh < 2; ++nh)
#pragma unroll
            for (int j = 0; j < 4; ++j) d[i][nh][j] = 0.0f;

#pragma unroll 1
    for (int dx = 0; dx < 3; ++dx) {
        // B fragments for the 3 dy-taps at this dx: one uint4 per lane each.
        uint32_t bh[3][2][2], bl[3][2][2];
#pragma unroll
        for (int dyi = 0; dyi < 3; ++dyi) {
            uint4 H = whq[(dyi * 3 + dx) * 32 + lane];
            uint4 L = wlq[(dyi * 3 + dx) * 32 + lane];
            bh[dyi][0][0] = H.x; bh[dyi][0][1] = H.y;
            bh[dyi][1][0] = H.z; bh[dyi][1][1] = H.w;
            bl[dyi][0][0] = L.x; bl[dyi][0][1] = L.y;
            bl[dyi][1][0] = L.z; bl[dyi][1][1] = L.w;
        }
#pragma unroll
        for (int ff = 0; ff < 8; ++ff) {
            const int f = ff - 2;
            int p = (base_blk + f) * 16 + 40 + (dx - 1) + l15;   // padded idx
            uint32_t addr = a_hh + p * 32 + ((hsel ^ ((p >> 2) & 1)) << 4);
            uint32_t A[4], AL[4];
            LDSM4(A, addr);
            LDSM4(AL, addr + (OFF_HL - OFF_HH));
            // dy=+1 -> block f-2 uses tap row 2; dy=0 -> f, row 1; dy=-1 -> f+2, row 0
            if (f - 2 >= 0 && f - 2 <= 3) { DO6(d[f - 2], A, AL, bh[2], bl[2]); }
            if (f     >= 0 && f     <= 3) { DO6(d[f],     A, AL, bh[1], bl[1]); }
            if (f + 2 >= 0 && f + 2 <= 3) { DO6(d[f + 2], A, AL, bh[0], bl[0]); }
        }
    }

    if (!FINAL) __syncthreads();   // all ldmatrix reads done before overwrite

    const int c0 = 2 * (lane & 3);
#pragma unroll
    for (int i = 0; i < 4; ++i) {
        int b = base_blk + i;
#pragma unroll
        for (int px = 0; px < 2; ++px) {
            int p = b * 16 + (lane >> 2) + px * 8;   // buffer pixel 0..767
            int rr = p >> 5, cc = p & 31;
            float v0 = d[i][0][2 * px], v1 = d[i][0][2 * px + 1];
            float v8 = d[i][1][2 * px], v9 = d[i][1][2 * px + 1];
            if (FINAL) {
                int gy = oy + rr - 2, gx = ox + cc - 2;
                if (rr >= 2 && rr < 22 && cc >= 2 && cc < 30 &&
                    gy < IMG && gx < IMG) {
                    float* ob = out + ((size_t)(bz * 16) * IMG + gy) * IMG + gx;
                    ob[(size_t)(c0)     * IMG * IMG] = fmaxf(v0, 0.0f);
                    ob[(size_t)(c0 + 1) * IMG * IMG] = fmaxf(v1, 0.0f);
                    ob[(size_t)(c0 + 8) * IMG * IMG] = fmaxf(v8, 0.0f);
                    ob[(size_t)(c0 + 9) * IMG * IMG] = fmaxf(v9, 0.0f);
                }
            } else {
                // per-layer SAME padding: zero outside image
                float mval = (((unsigned)(oy + rr - 2) < IMG) &&
                              (((unsigned)(ox + cc - 2)) < IMG)) ? 1.0f : 0.0f;
                v0 *= mval; v1 *= mval; v8 *= mval; v9 *= mval;
                __half h0 = __float2half_rn(v0), h1 = __float2half_rn(v1);
                __half h8 = __float2half_rn(v8), h9 = __float2half_rn(v9);
                __half e0 = __float2half_rn(v0 - __half2float(h0));
                __half e1 = __float2half_rn(v1 - __half2float(h1));
                __half e8 = __float2half_rn(v8 - __half2float(h8));
                __half e9 = __float2half_rn(v9 - __half2float(h9));
                int pp = p + 40;
                int s = (pp >> 2) & 1;
                char* rb = smc + OFF_HH + pp * 32;
                *(uint32_t*)(rb + (s << 4)       + c0 * 2) = packh2(h0, h1);
                *(uint32_t*)(rb + ((1 ^ s) << 4) + c0 * 2) = packh2(h8, h9);
                rb += (OFF_HL - OFF_HH);
                *(uint32_t*)(rb + (s << 4)       + c0 * 2) = packh2(e0, e1);
                *(uint32_t*)(rb + ((1 ^ s) << 4) + c0 * 2) = packh2(e8, e9);
            }
        }
    }
}

__global__ __launch_bounds__(NTHR, 2)
void net_fused_kernel(const float* __restrict__ x,
                      const float* __restrict__ w1,
                      const float* __restrict__ w2,
                      const float* __restrict__ w3,
                      float* __restrict__ out) {
    extern __shared__ char smc[];
    const int tid  = threadIdx.x;
    const int lane = tid & 31;
    const int wid  = tid >> 5;
    const int ox = blockIdx.x * TOX;
    const int oy = blockIdx.y * TOY;
    const int bz = blockIdx.z;

    float*  s_in = (float*)(smc + OFF_IN);
    float*  s_w1 = (float*)(smc + OFF_W1);
    __half* w2h  = (__half*)(smc + OFF_W2H);
    __half* w2l  = (__half*)(smc + OFF_W2L);
    __half* w3h  = (__half*)(smc + OFF_W3H);
    __half* w3l  = (__half*)(smc + OFF_W3L);

    // ---- Stage A: input halo (3 x 26 x 34, stride 36) + weights + pads ----
    {
        const float* xb = x + (size_t)bz * 3 * IMG * IMG;
        for (int i = tid; i < 3 * 26 * 34; i += NTHR) {
            int cin = i / 884;
            int rem = i - cin * 884;
            int rr = rem / 34, cc = rem - rr * 34;
            int gy = oy - 3 + rr, gx = ox - 3 + cc;
            float v = 0.0f;
            if ((unsigned)gy < IMG && (unsigned)gx < IMG)
                v = xb[(size_t)cin * IMG * IMG + (size_t)gy * IMG + gx];
            s_in[cin * 936 + rr * 36 + cc] = v;
        }
        for (int i = tid; i < 432; i += NTHR)
            s_w1[i] = w1[(i & 15) * 27 + (i >> 4)];
        // conv2/3 weights, uint4-per-lane fragment order:
        //   element (tap, n, k): lane=(n&7)*4+((k>>1)&3), word j=(n>>3)*2+((k>>3)&1)
        //   half index = ((tap*32+lane)*4 + j)*2 + (k&1)
        for (int i = tid; i < 2304; i += NTHR) {
            int tap = i >> 8, n = (i >> 4) & 15, k = i & 15;
            int lane_b = ((n & 7) << 2) + ((k >> 1) & 3);
            int j = ((n >> 3) << 1) + ((k >> 3) & 1);
            int hidx = (((tap * 32 + lane_b) << 2) + j) * 2 + (k & 1);
            float v2 = w2[n * 144 + k * 9 + tap];
            float v3 = w3[n * 144 + k * 9 + tap];
            __half a2 = __float2half_rn(v2);
            __half a3 = __float2half_rn(v3);
            w2h[hidx] = a2;  w2l[hidx] = __float2half_rn(v2 - __half2float(a2));
            w3h[hidx] = a3;  w3l[hidx] = __float2half_rn(v3 - __half2float(a3));
        }
        // zero pad pixel rows: padded idx 0..39 and 808..847
        for (int p = tid; p < 80; p += NTHR) {
            int pp = (p < 40) ? p : (768 + p);   // 808..847
            *(uint4*)(smc + OFF_HH + pp * 32)      = make_uint4(0, 0, 0, 0);
            *(uint4*)(smc + OFF_HH + pp * 32 + 16) = make_uint4(0, 0, 0, 0);
            *(uint4*)(smc + OFF_HL + pp * 32)      = make_uint4(0, 0, 0, 0);
            *(uint4*)(smc + OFF_HL + pp * 32 + 16) = make_uint4(0, 0, 0, 0);
        }
    }
    __syncthreads();

    // ---- Stage B: conv1 (3->16) FFMA2 over 24x32 buffer, split f16 store ----
#pragma unroll 1
    for (int m = tid; m < 768; m += NTHR) {
        int rr = m >> 5, cc = m & 31;
        ull acc[8];
#pragma unroll
        for (int q = 0; q < 8; ++q) acc[q] = 0ULL;
#pragma unroll
        for (int cin = 0; cin < 3; ++cin) {
            const float* bp = s_in + cin * 936 + rr * 36 + cc;
            float a[9];
#pragma unroll
            for (int dy = 0; dy < 3; ++dy) {
                a[dy * 3 + 0] = bp[dy * 36 + 0];
                a[dy * 3 + 1] = bp[dy * 36 + 1];
                a[dy * 3 + 2] = bp[dy * 36 + 2];
            }
            const ulonglong2* w = (const ulonglong2*)s_w1 + cin * 36;
#pragma unroll
            for (int t = 0; t < 9; ++t) {
                ull dup = pk2(a[t], a[t]);
#pragma unroll
                for (int j = 0; j < 4; ++j) {
                    ulonglong2 wv = w[t * 4 + j];
                    ffma2(acc[2 * j],     dup, wv.x);
                    ffma2(acc[2 * j + 1], dup, wv.y);
                }
            }
        }
        float mval = (((unsigned)(oy + rr - 2) < IMG) &&
                      (((unsigned)(ox + cc - 2)) < IMG)) ? 1.0f : 0.0f;
        float v[16];
#pragma unroll
        for (int q = 0; q < 8; ++q) {
            unpk2(acc[q], v[2 * q], v[2 * q + 1]);
            v[2 * q] *= mval; v[2 * q + 1] *= mval;
        }
        uint32_t hi[8], lo[8];
#pragma unroll
        for (int j = 0; j < 8; ++j) {
            __half a0 = __float2half_rn(v[2 * j]);
            __half a1 = __float2half_rn(v[2 * j + 1]);
            __half e0 = __float2half_rn(v[2 * j]     - __half2float(a0));
            __half e1 = __float2half_rn(v[2 * j + 1] - __half2float(a1));
            hi[j] = packh2(a0, a1);
            lo[j] = packh2(e0, e1);
        }
        int pp = m + 40;
        int s = (pp >> 2) & 1;
        char* rb = smc + OFF_HH + pp * 32;
        *(uint4*)(rb + (s << 4))       = make_uint4(hi[0], hi[1], hi[2], hi[3]);
        *(uint4*)(rb + ((1 ^ s) << 4)) = make_uint4(hi[4], hi[5], hi[6], hi[7]);
        rb += (OFF_HL - OFF_HH);
        *(uint4*)(rb + (s << 4))       = make_uint4(lo[0], lo[1], lo[2], lo[3]);
        *(uint4*)(rb + ((1 ^ s) << 4)) = make_uint4(lo[4], lo[5], lo[6], lo[7]);
    }
    __syncthreads();

    // ---- Stage C: conv2 via mma.sync (writes h buffers back) ----
    mma_layer<false>(smc, lane, wid, OFF_W2H, OFF_W2L, ox, oy, bz, out);
    __syncthreads();

    // ---- Stage D: conv3 via mma.sync + ReLU -> global ----
    mma_layer<true>(smc, lane, wid, OFF_W3H, OFF_W3L, ox, oy, bz, out);
}

extern "C" void kernel_launch(void* const* d_in, const int* in_sizes, int n_in,
                              void* d_out, int out_size) {
    const float* x  = (const float*)d_in[0];
    const float* w1 = (const float*)d_in[1];
    const float* w2 = (const float*)d_in[2];
    const float* w3 = (const float*)d_in[3];
    float* out = (float*)d_out;

    cudaFuncSetAttribute(net_fused_kernel,
                         cudaFuncAttributeMaxDynamicSharedMemorySize, SMEM_BYTES);

    dim3 grid(NTX, NTY, NB);
    net_fused_kernel<<<grid, NTHR, SMEM_BYTES>>>(x, w1, w2, w3, out);
}

// round 15
// speedup vs baseline: 2.8236x; 1.2065x over previous
#include <cuda_runtime.h>
#include <cuda_fp16.h>
#include <cstdint>

#define IMG   1536
#define NB    4
#define TOX   28          // output tile width  (buffer 32 cols)
#define TOY   20          // output tile height (buffer 24 rows)
#define NTX   55
#define NTY   77
#define NTHR  384

typedef unsigned long long ull;

// ---- byte offsets in dynamic smem ----
// h: 848 padded pixel rows (40 pad + 768 + 40 pad) * 32 B (16 f16 ch)
#define OFF_HH   0
#define OFF_W2H  27136    // 9 taps * 32 lanes * 16 B = 4608 B each
#define OFF_W2L  31744
#define OFF_W3H  36352
#define OFF_W3L  40960
#define OFF_W1   45568    // 432 f32
#define OFF_IN   47296    // 3 * 26 * 36 f32 = 11232 B
#define SMEM_BYTES 58528

// ---------------- helpers ----------------
__device__ __forceinline__ ull pk2(float lo, float hi) {
    ull r; asm("mov.b64 %0, {%1, %2};" : "=l"(r) : "f"(lo), "f"(hi)); return r;
}
__device__ __forceinline__ void ffma2(ull& d, ull a, ull b) {
    asm("fma.rn.f32x2 %0, %1, %2, %0;" : "+l"(d) : "l"(a), "l"(b));
}
__device__ __forceinline__ void unpk2(ull v, float& lo, float& hi) {
    asm("mov.b64 {%0, %1}, %2;" : "=f"(lo), "=f"(hi) : "l"(v));
}
__device__ __forceinline__ uint32_t smem_u32(const void* p) {
    uint32_t a;
    asm("{ .reg .u64 t; cvta.to.shared.u64 t, %1; cvt.u32.u64 %0, t; }" : "=r"(a) : "l"(p));
    return a;
}
__device__ __forceinline__ uint32_t packh2(__half a, __half b) {
    __half2 t = __halves2half2(a, b);
    return *reinterpret_cast<uint32_t*>(&t);
}

#define LDSM4(R, ADDR) \
    asm volatile("ldmatrix.sync.aligned.m8n8.x4.shared.b16 {%0,%1,%2,%3}, [%4];" \
        : "=r"((R)[0]), "=r"((R)[1]), "=r"((R)[2]), "=r"((R)[3]) : "r"(ADDR))

#define MMA16816(D, A, B0, B1) \
    asm volatile("mma.sync.aligned.m16n8k16.row.col.f32.f16.f16.f32 " \
        "{%0,%1,%2,%3}, {%4,%5,%6,%7}, {%8,%9}, {%0,%1,%2,%3};" \
        : "+f"((D)[0]), "+f"((D)[1]), "+f"((D)[2]), "+f"((D)[3]) \
        : "r"((A)[0]), "r"((A)[1]), "r"((A)[2]), "r"((A)[3]), "r"(B0), "r"(B1))

// A plain fp16, W 2-term split: D += A*Bh + A*Bl  (both n-halves)
#define DO4(DACC, A, BH, BL) \
    MMA16816((DACC)[0], A, (BH)[0][0], (BH)[0][1]); \
    MMA16816((DACC)[1], A, (BH)[1][0], (BH)[1][1]); \
    MMA16816((DACC)[0], A, (BL)[0][0], (BL)[0][1]); \
    MMA16816((DACC)[1], A, (BL)[1][0], (BL)[1][1]);

// One conv layer as implicit GEMM over the 768-pixel buffer.
// Each warp owns 4 CONSECUTIVE M-blocks (b = 4*wid .. 4*wid+3, 16 px each).
// Buffer row = 32 px = 2 blocks, so tap (dy,dx) of block b reads the same A
// fragment as tap (0,dx) of block b+2dy: fragment id f = b + 2*dy.
// Stream f = -2..5 per dx: each fragment loaded ONCE, feeds up to 3 blocks.
template<bool FINAL>
__device__ __forceinline__ void mma_layer(char* smc, int lane, int wid,
                                          int whOff, int wlOff,
                                          int ox, int oy, int bz,
                                          float* __restrict__ out) {
    const uint32_t a_hh = smem_u32(smc + OFF_HH);
    const uint4* whq = (const uint4*)(smc + whOff);
    const uint4* wlq = (const uint4*)(smc + wlOff);
    const int l15 = lane & 15;
    const int hsel = lane >> 4;            // which 16B half (ch 0-7 / 8-15)
    const int base_blk = wid * 4;

    float d[4][2][4];
#pragma unroll
    for (int i = 0; i < 4; ++i)
#pragma unroll
        for (int nh = 0; nh < 2; ++nh)
#pragma unroll
            for (int j = 0; j < 4; ++j) d[i][nh][j] = 0.0f;

#pragma unroll 1
    for (int dx = 0; dx < 3; ++dx) {
        // B fragments for the 3 dy-taps at this dx: one uint4 per lane each.
        uint32_t bh[3][2][2], bl[3][2][2];
#pragma unroll
        for (int dyi = 0; dyi < 3; ++dyi) {
            uint4 H = whq[(dyi * 3 + dx) * 32 + lane];
            uint4 L = wlq[(dyi * 3 + dx) * 32 + lane];
            bh[dyi][0][0] = H.x; bh[dyi][0][1] = H.y;
            bh[dyi][1][0] = H.z; bh[dyi][1][1] = H.w;
            bl[dyi][0][0] = L.x; bl[dyi][0][1] = L.y;
            bl[dyi][1][0] = L.z; bl[dyi][1][1] = L.w;
        }
#pragma unroll
        for (int ff = 0; ff < 8; ++ff) {
            const int f = ff - 2;
            int p = (base_blk + f) * 16 + 40 + (dx - 1) + l15;   // padded idx
            uint32_t addr = a_hh + p * 32 + ((hsel ^ ((p >> 2) & 1)) << 4);
            uint32_t A[4];
            LDSM4(A, addr);
            // dy=+1 -> block f-2 (tap row 2); dy=0 -> f (row 1); dy=-1 -> f+2 (row 0)
            if (f - 2 >= 0 && f - 2 <= 3) { DO4(d[f - 2], A, bh[2], bl[2]); }
            if (f     >= 0 && f     <= 3) { DO4(d[f],     A, bh[1], bl[1]); }
            if (f + 2 >= 0 && f + 2 <= 3) { DO4(d[f + 2], A, bh[0], bl[0]); }
        }
    }

    if (!FINAL) __syncthreads();   // all ldmatrix reads done before overwrite

    const int c0 = 2 * (lane & 3);
#pragma unroll
    for (int i = 0; i < 4; ++i) {
        int b = base_blk + i;
#pragma unroll
        for (int px = 0; px < 2; ++px) {
            int p = b * 16 + (lane >> 2) + px * 8;   // buffer pixel 0..767
            int rr = p >> 5, cc = p & 31;
            float v0 = d[i][0][2 * px], v1 = d[i][0][2 * px + 1];
            float v8 = d[i][1][2 * px], v9 = d[i][1][2 * px + 1];
            if (FINAL) {
                int gy = oy + rr - 2, gx = ox + cc - 2;
                if (rr >= 2 && rr < 22 && cc >= 2 && cc < 30 &&
                    gy < IMG && gx < IMG) {
                    float* ob = out + ((size_t)(bz * 16) * IMG + gy) * IMG + gx;
                    ob[(size_t)(c0)     * IMG * IMG] = fmaxf(v0, 0.0f);
                    ob[(size_t)(c0 + 1) * IMG * IMG] = fmaxf(v1, 0.0f);
                    ob[(size_t)(c0 + 8) * IMG * IMG] = fmaxf(v8, 0.0f);
                    ob[(size_t)(c0 + 9) * IMG * IMG] = fmaxf(v9, 0.0f);
                }
            } else {
                // per-layer SAME padding: zero outside image
                float mval = (((unsigned)(oy + rr - 2) < IMG) &&
                              (((unsigned)(ox + cc - 2)) < IMG)) ? 1.0f : 0.0f;
                v0 *= mval; v1 *= mval; v8 *= mval; v9 *= mval;
                int pp = p + 40;
                int s = (pp >> 2) & 1;
                char* rb = smc + OFF_HH + pp * 32;
                *(uint32_t*)(rb + (s << 4)       + c0 * 2) =
                    packh2(__float2half_rn(v0), __float2half_rn(v1));
                *(uint32_t*)(rb + ((1 ^ s) << 4) + c0 * 2) =
                    packh2(__float2half_rn(v8), __float2half_rn(v9));
            }
        }
    }
}

__global__ __launch_bounds__(NTHR, 2)
void net_fused_kernel(const float* __restrict__ x,
                      const float* __restrict__ w1,
                      const float* __restrict__ w2,
                      const float* __restrict__ w3,
                      float* __restrict__ out) {
    extern __shared__ char smc[];
    const int tid  = threadIdx.x;
    const int lane = tid & 31;
    const int wid  = tid >> 5;
    const int ox = blockIdx.x * TOX;
    const int oy = blockIdx.y * TOY;
    const int bz = blockIdx.z;

    float*  s_in = (float*)(smc + OFF_IN);
    float*  s_w1 = (float*)(smc + OFF_W1);
    __half* w2h  = (__half*)(smc + OFF_W2H);
    __half* w2l  = (__half*)(smc + OFF_W2L);
    __half* w3h  = (__half*)(smc + OFF_W3H);
    __half* w3l  = (__half*)(smc + OFF_W3L);

    // ---- Stage A: input halo (3 x 26 x 34, stride 36) + weights + pads ----
    {
        const float* xb = x + (size_t)bz * 3 * IMG * IMG;
        for (int i = tid; i < 3 * 26 * 34; i += NTHR) {
            int cin = i / 884;
            int rem = i - cin * 884;
            int rr = rem / 34, cc = rem - rr * 34;
            int gy = oy - 3 + rr, gx = ox - 3 + cc;
            float v = 0.0f;
            if ((unsigned)gy < IMG && (unsigned)gx < IMG)
                v = xb[(size_t)cin * IMG * IMG + (size_t)gy * IMG + gx];
            s_in[cin * 936 + rr * 36 + cc] = v;
        }
        for (int i = tid; i < 432; i += NTHR)
            s_w1[i] = w1[(i & 15) * 27 + (i >> 4)];
        // conv2/3 weights, uint4-per-lane fragment order:
        //   element (tap, n, k): lane=(n&7)*4+((k>>1)&3), word j=(n>>3)*2+((k>>3)&1)
        //   half index = ((tap*32+lane)*4 + j)*2 + (k&1)
        for (int i = tid; i < 2304; i += NTHR) {
            int tap = i >> 8, n = (i >> 4) & 15, k = i & 15;
            int lane_b = ((n & 7) << 2) + ((k >> 1) & 3);
            int j = ((n >> 3) << 1) + ((k >> 3) & 1);
            int hidx = (((tap * 32 + lane_b) << 2) + j) * 2 + (k & 1);
            float v2 = w2[n * 144 + k * 9 + tap];
            float v3 = w3[n * 144 + k * 9 + tap];
            __half a2 = __float2half_rn(v2);
            __half a3 = __float2half_rn(v3);
            w2h[hidx] = a2;  w2l[hidx] = __float2half_rn(v2 - __half2float(a2));
            w3h[hidx] = a3;  w3l[hidx] = __float2half_rn(v3 - __half2float(a3));
        }
        // zero pad pixel rows: padded idx 0..39 and 808..847
        for (int p = tid; p < 80; p += NTHR) {
            int pp = (p < 40) ? p : (768 + p);   // 808..847
            *(uint4*)(smc + OFF_HH + pp * 32)      = make_uint4(0, 0, 0, 0);
            *(uint4*)(smc + OFF_HH + pp * 32 + 16) = make_uint4(0, 0, 0, 0);
        }
    }
    __syncthreads();

    // ---- Stage B: conv1 (3->16) FFMA2 over 24x32 buffer, fp16 store ----
#pragma unroll 1
    for (int m = tid; m < 768; m += NTHR) {
        int rr = m >> 5, cc = m & 31;
        ull acc[8];
#pragma unroll
        for (int q = 0; q < 8; ++q) acc[q] = 0ULL;
#pragma unroll
        for (int cin = 0; cin < 3; ++cin) {
            const float* bp = s_in + cin * 936 + rr * 36 + cc;
            float a[9];
#pragma unroll
            for (int dy = 0; dy < 3; ++dy) {
                a[dy * 3 + 0] = bp[dy * 36 + 0];
                a[dy * 3 + 1] = bp[dy * 36 + 1];
                a[dy * 3 + 2] = bp[dy * 36 + 2];
            }
            const ulonglong2* w = (const ulonglong2*)s_w1 + cin * 36;
#pragma unroll
            for (int t = 0; t < 9; ++t) {
                ull dup = pk2(a[t], a[t]);
#pragma unroll
                for (int j = 0; j < 4; ++j) {
                    ulonglong2 wv = w[t * 4 + j];
                    ffma2(acc[2 * j],     dup, wv.x);
                    ffma2(acc[2 * j + 1], dup, wv.y);
                }
            }
        }
        float mval = (((unsigned)(oy + rr - 2) < IMG) &&
                      (((unsigned)(ox + cc - 2)) < IMG)) ? 1.0f : 0.0f;
        uint32_t hi[8];
#pragma unroll
        for (int q = 0; q < 8; ++q) {
            float v0, v1;
            unpk2(acc[q], v0, v1);
            hi[q] = packh2(__float2half_rn(v0 * mval), __float2half_rn(v1 * mval));
        }
        int pp = m + 40;
        int s = (pp >> 2) & 1;
        char* rb = smc + OFF_HH + pp * 32;
        *(uint4*)(rb + (s << 4))       = make_uint4(hi[0], hi[1], hi[2], hi[3]);
        *(uint4*)(rb + ((1 ^ s) << 4)) = make_uint4(hi[4], hi[5], hi[6], hi[7]);
    }
    __syncthreads();

    // ---- Stage C: conv2 via mma.sync (writes h buffer back) ----
    mma_layer<false>(smc, lane, wid, OFF_W2H, OFF_W2L, ox, oy, bz, out);
    __syncthreads();

    // ---- Stage D: conv3 via mma.sync + ReLU -> global ----
    mma_layer<true>(smc, lane, wid, OFF_W3H, OFF_W3L, ox, oy, bz, out);
}

extern "C" void kernel_launch(void* const* d_in, const int* in_sizes, int n_in,
                              void* d_out, int out_size) {
    const float* x  = (const float*)d_in[0];
    const float* w1 = (const float*)d_in[1];
    const float* w2 = (const float*)d_in[2];
    const float* w3 = (const float*)d_in[3];
    float* out = (float*)d_out;

    cudaFuncSetAttribute(net_fused_kernel,
                         cudaFuncAttributeMaxDynamicSharedMemorySize, SMEM_BYTES);

    dim3 grid(NTX, NTY, NB);
    net_fused_kernel<<<grid, NTHR, SMEM_BYTES>>>(x, w1, w2, w3, out);
}

// round 17
// speedup vs baseline: 3.3167x; 1.1747x over previous
#include <cuda_runtime.h>
#include <cuda_fp16.h>
#include <cstdint>

#define IMG   1536
#define NB    4
#define TOX   28          // output tile width  (buffer 32 cols)
#define TOY   20          // output tile height (buffer 24 rows)
#define NTX   55
#define NTY   77
#define NTHR  384

// ---- byte offsets in dynamic smem ----
// HH: 848 padded pixel rows (40 pad + 768 + 40 pad) * 32 B (16 f16 ch)
// AB0/AB1: conv1 im2col k-groups, 768 rows * 32 B each
#define OFF_HH   0
#define OFF_AB0  27136
#define OFF_AB1  51712
#define OFF_W2H  76288    // 9 taps * 32 lanes * 16 B = 4608 B each
#define OFF_W2L  80896
#define OFF_W3H  85504
#define OFF_W3L  90112
#define OFF_W1H  94720    // 2 ks * 32 lanes * 16 B = 1024 B each
#define OFF_W1L  95744
#define OFF_IN   96768    // 3 * 26 * 36 f32 = 11232 B
#define SMEM_BYTES 108000

// ---------------- helpers ----------------
__device__ __forceinline__ uint32_t smem_u32(const void* p) {
    uint32_t a;
    asm("{ .reg .u64 t; cvta.to.shared.u64 t, %1; cvt.u32.u64 %0, t; }" : "=r"(a) : "l"(p));
    return a;
}
__device__ __forceinline__ uint32_t packh2(__half a, __half b) {
    __half2 t = __halves2half2(a, b);
    return *reinterpret_cast<uint32_t*>(&t);
}

#define LDSM4(R, ADDR) \
    asm volatile("ldmatrix.sync.aligned.m8n8.x4.shared.b16 {%0,%1,%2,%3}, [%4];" \
        : "=r"((R)[0]), "=r"((R)[1]), "=r"((R)[2]), "=r"((R)[3]) : "r"(ADDR))

#define MMA16816(D, A, B0, B1) \
    asm volatile("mma.sync.aligned.m16n8k16.row.col.f32.f16.f16.f32 " \
        "{%0,%1,%2,%3}, {%4,%5,%6,%7}, {%8,%9}, {%0,%1,%2,%3};" \
        : "+f"((D)[0]), "+f"((D)[1]), "+f"((D)[2]), "+f"((D)[3]) \
        : "r"((A)[0]), "r"((A)[1]), "r"((A)[2]), "r"((A)[3]), "r"(B0), "r"(B1))

// A plain fp16, W 2-term split: D += A*Bh + A*Bl  (both n-halves)
#define DO4(DACC, A, BH, BL) \
    MMA16816((DACC)[0], A, (BH)[0][0], (BH)[0][1]); \
    MMA16816((DACC)[1], A, (BH)[1][0], (BH)[1][1]); \
    MMA16816((DACC)[0], A, (BL)[0][0], (BL)[0][1]); \
    MMA16816((DACC)[1], A, (BL)[1][0], (BL)[1][1]);

// Masked fp16 epilogue store of one warp's 4 blocks into the HH buffer.
__device__ __forceinline__ void epi_store_h(char* smc, int lane, int base_blk,
                                            int ox, int oy, float d[4][2][4]) {
    const int c0 = 2 * (lane & 3);
#pragma unroll
    for (int i = 0; i < 4; ++i) {
        int b = base_blk + i;
#pragma unroll
        for (int px = 0; px < 2; ++px) {
            int p = b * 16 + (lane >> 2) + px * 8;   // buffer pixel 0..767
            int rr = p >> 5, cc = p & 31;
            // per-layer SAME padding: zero outside image
            float mval = (((unsigned)(oy + rr - 2) < IMG) &&
                          (((unsigned)(ox + cc - 2)) < IMG)) ? 1.0f : 0.0f;
            float v0 = d[i][0][2 * px] * mval, v1 = d[i][0][2 * px + 1] * mval;
            float v8 = d[i][1][2 * px] * mval, v9 = d[i][1][2 * px + 1] * mval;
            int pp = p + 40;
            int s = (pp >> 2) & 1;
            char* rb = smc + OFF_HH + pp * 32;
            *(uint32_t*)(rb + (s << 4)       + c0 * 2) =
                packh2(__float2half_rn(v0), __float2half_rn(v1));
            *(uint32_t*)(rb + ((1 ^ s) << 4) + c0 * 2) =
                packh2(__float2half_rn(v8), __float2half_rn(v9));
        }
    }
}

// conv2/conv3 layer as implicit GEMM over the 768-pixel buffer.
// Each warp owns 4 CONSECUTIVE M-blocks. Buffer row = 32 px = 2 blocks, so
// tap (dy,dx) of block b reads the same A fragment as tap (0,dx) of block
// b+2dy: fragment id f = b + 2*dy. Stream f = -2..5 per dx.
template<bool FINAL>
__device__ __forceinline__ void mma_layer(char* smc, int lane, int wid,
                                          int whOff, int wlOff,
                                          int ox, int oy, int bz,
                                          float* __restrict__ out) {
    const uint32_t a_hh = smem_u32(smc + OFF_HH);
    const uint4* whq = (const uint4*)(smc + whOff);
    const uint4* wlq = (const uint4*)(smc + wlOff);
    const int l15 = lane & 15;
    const int hsel = lane >> 4;            // which 16B half (ch 0-7 / 8-15)
    const int base_blk = wid * 4;

    float d[4][2][4];
#pragma unroll
    for (int i = 0; i < 4; ++i)
#pragma unroll
        for (int nh = 0; nh < 2; ++nh)
#pragma unroll
            for (int j = 0; j < 4; ++j) d[i][nh][j] = 0.0f;

#pragma unroll 1
    for (int dx = 0; dx < 3; ++dx) {
        uint32_t bh[3][2][2], bl[3][2][2];
#pragma unroll
        for (int dyi = 0; dyi < 3; ++dyi) {
            uint4 H = whq[(dyi * 3 + dx) * 32 + lane];
            uint4 L = wlq[(dyi * 3 + dx) * 32 + lane];
            bh[dyi][0][0] = H.x; bh[dyi][0][1] = H.y;
            bh[dyi][1][0] = H.z; bh[dyi][1][1] = H.w;
            bl[dyi][0][0] = L.x; bl[dyi][0][1] = L.y;
            bl[dyi][1][0] = L.z; bl[dyi][1][1] = L.w;
        }
#pragma unroll
        for (int ff = 0; ff < 8; ++ff) {
            const int f = ff - 2;
            int p = (base_blk + f) * 16 + 40 + (dx - 1) + l15;   // padded idx
            uint32_t addr = a_hh + p * 32 + ((hsel ^ ((p >> 2) & 1)) << 4);
            uint32_t A[4];
            LDSM4(A, addr);
            if (f - 2 >= 0 && f - 2 <= 3) { DO4(d[f - 2], A, bh[2], bl[2]); }
            if (f     >= 0 && f     <= 3) { DO4(d[f],     A, bh[1], bl[1]); }
            if (f + 2 >= 0 && f + 2 <= 3) { DO4(d[f + 2], A, bh[0], bl[0]); }
        }
    }

    if (!FINAL) __syncthreads();   // all ldmatrix reads done before overwrite

    if (FINAL) {
        const int c0 = 2 * (lane & 3);
#pragma unroll
        for (int i = 0; i < 4; ++i) {
            int b = base_blk + i;
#pragma unroll
            for (int px = 0; px < 2; ++px) {
                int p = b * 16 + (lane >> 2) + px * 8;
                int rr = p >> 5, cc = p & 31;
                int gy = oy + rr - 2, gx = ox + cc - 2;
                if (rr >= 2 && rr < 22 && cc >= 2 && cc < 30 &&
                    gy < IMG && gx < IMG) {
                    float* ob = out + ((size_t)(bz * 16) * IMG + gy) * IMG + gx;
                    ob[(size_t)(c0)     * IMG * IMG] = fmaxf(d[i][0][2*px], 0.0f);
                    ob[(size_t)(c0 + 1) * IMG * IMG] = fmaxf(d[i][0][2*px+1], 0.0f);
                    ob[(size_t)(c0 + 8) * IMG * IMG] = fmaxf(d[i][1][2*px], 0.0f);
                    ob[(size_t)(c0 + 9) * IMG * IMG] = fmaxf(d[i][1][2*px+1], 0.0f);
                }
            }
        }
    } else {
        epi_store_h(smc, lane, base_blk, ox, oy, d);
    }
}

__global__ __launch_bounds__(NTHR, 2)
void net_fused_kernel(const float* __restrict__ x,
                      const float* __restrict__ w1,
                      const float* __restrict__ w2,
                      const float* __restrict__ w3,
                      float* __restrict__ out) {
    extern __shared__ char smc[];
    const int tid  = threadIdx.x;
    const int lane = tid & 31;
    const int wid  = tid >> 5;
    const int ox = blockIdx.x * TOX;
    const int oy = blockIdx.y * TOY;
    const int bz = blockIdx.z;

    float*  s_in = (float*)(smc + OFF_IN);
    __half* w1h  = (__half*)(smc + OFF_W1H);
    __half* w1l  = (__half*)(smc + OFF_W1L);
    __half* w2h  = (__half*)(smc + OFF_W2H);
    __half* w2l  = (__half*)(smc + OFF_W2L);
    __half* w3h  = (__half*)(smc + OFF_W3H);
    __half* w3l  = (__half*)(smc + OFF_W3L);

    // ---- Stage A: input halo (3 x 26 x 34, stride 36) + weights + pads ----
    {
        const float* xb = x + (size_t)bz * 3 * IMG * IMG;
        for (int i = tid; i < 3 * 26 * 34; i += NTHR) {
            int cin = i / 884;
            int rem = i - cin * 884;
            int rr = rem / 34, cc = rem - rr * 34;
            int gy = oy - 3 + rr, gx = ox - 3 + cc;
            float v = 0.0f;
            if ((unsigned)gy < IMG && (unsigned)gx < IMG)
                v = xb[(size_t)cin * IMG * IMG + (size_t)gy * IMG + gx];
            s_in[cin * 936 + rr * 36 + cc] = v;
        }
        // conv1 weights as 2 k-step fragments (K=27 padded to 32), split
        for (int i = tid; i < 512; i += NTHR) {
            int ks = i >> 8, n = (i >> 4) & 15, kl = i & 15;
            int k = ks * 16 + kl;
            float v = (k < 27) ? w1[n * 27 + k] : 0.0f;
            int lane_b = ((n & 7) << 2) + ((kl >> 1) & 3);
            int j = ((n >> 3) << 1) + ((kl >> 3) & 1);
            int hidx = (((ks * 32 + lane_b) << 2) + j) * 2 + (kl & 1);
            __half a = __float2half_rn(v);
            w1h[hidx] = a;
            w1l[hidx] = __float2half_rn(v - __half2float(a));
        }
        // conv2/3 weights, uint4-per-lane fragment order
        for (int i = tid; i < 2304; i += NTHR) {
            int tap = i >> 8, n = (i >> 4) & 15, k = i & 15;
            int lane_b = ((n & 7) << 2) + ((k >> 1) & 3);
            int j = ((n >> 3) << 1) + ((k >> 3) & 1);
            int hidx = (((tap * 32 + lane_b) << 2) + j) * 2 + (k & 1);
            float v2 = w2[n * 144 + k * 9 + tap];
            float v3 = w3[n * 144 + k * 9 + tap];
            __half a2 = __float2half_rn(v2);
            __half a3 = __float2half_rn(v3);
            w2h[hidx] = a2;  w2l[hidx] = __float2half_rn(v2 - __half2float(a2));
            w3h[hidx] = a3;  w3l[hidx] = __float2half_rn(v3 - __half2float(a3));
        }
        // zero HH pad pixel rows: padded idx 0..39 and 808..847
        for (int p = tid; p < 80; p += NTHR) {
            int pp = (p < 40) ? p : (768 + p);   // 808..847
            *(uint4*)(smc + OFF_HH + pp * 32)      = make_uint4(0, 0, 0, 0);
            *(uint4*)(smc + OFF_HH + pp * 32 + 16) = make_uint4(0, 0, 0, 0);
        }
    }
    __syncthreads();

    // ---- Stage B: build conv1 im2col (K=32, two 16-wide k-groups) ----
#pragma unroll 1
    for (int m = tid; m < 768; m += NTHR) {
        int rr = m >> 5, cc = m & 31;
        const float* base = s_in + rr * 36 + cc;
        float vals[27];
#pragma unroll
        for (int cin = 0; cin < 3; ++cin)
#pragma unroll
            for (int dy = 0; dy < 3; ++dy)
#pragma unroll
                for (int dxx = 0; dxx < 3; ++dxx)
                    vals[cin * 9 + dy * 3 + dxx] = base[cin * 936 + dy * 36 + dxx];
        uint32_t wds[16];
#pragma unroll
        for (int kk = 0; kk < 13; ++kk)
            wds[kk] = packh2(__float2half_rn(vals[2 * kk]),
                             __float2half_rn(vals[2 * kk + 1]));
        wds[13] = packh2(__float2half_rn(vals[26]), __float2half_rn(0.0f));
        wds[14] = 0u;
        wds[15] = 0u;
        int s = (m >> 2) & 1;
        char* r0 = smc + OFF_AB0 + m * 32;
        *(uint4*)(r0 + (s << 4))       = make_uint4(wds[0], wds[1], wds[2], wds[3]);
        *(uint4*)(r0 + ((1 ^ s) << 4)) = make_uint4(wds[4], wds[5], wds[6], wds[7]);
        char* r1 = smc + OFF_AB1 + m * 32;
        *(uint4*)(r1 + (s << 4))       = make_uint4(wds[8], wds[9], wds[10], wds[11]);
        *(uint4*)(r1 + ((1 ^ s) << 4)) = make_uint4(wds[12], wds[13], wds[14], wds[15]);
    }
    __syncthreads();

    // ---- Stage C: conv1 via mma.sync (A = im2col, 2 k-steps) -> HH ----
    {
        const uint32_t ab0 = smem_u32(smc + OFF_AB0);
        const uint32_t ab1 = smem_u32(smc + OFF_AB1);
        const uint4* w1hq = (const uint4*)(smc + OFF_W1H);
        const uint4* w1lq = (const uint4*)(smc + OFF_W1L);
        const int l15 = lane & 15;
        const int hsel = lane >> 4;
        const int base_blk = wid * 4;

        uint32_t bh1[2][2][2], bl1[2][2][2];
#pragma unroll
        for (int ks = 0; ks < 2; ++ks) {
            uint4 H = w1hq[ks * 32 + lane];
            uint4 L = w1lq[ks * 32 + lane];
            bh1[ks][0][0] = H.x; bh1[ks][0][1] = H.y;
            bh1[ks][1][0] = H.z; bh1[ks][1][1] = H.w;
            bl1[ks][0][0] = L.x; bl1[ks][0][1] = L.y;
            bl1[ks][1][0] = L.z; bl1[ks][1][1] = L.w;
        }

        float d[4][2][4];
#pragma unroll
        for (int i = 0; i < 4; ++i)
#pragma unroll
            for (int nh = 0; nh < 2; ++nh)
#pragma unroll
                for (int j = 0; j < 4; ++j) d[i][nh][j] = 0.0f;

#pragma unroll
        for (int i = 0; i < 4; ++i) {
            int q = (base_blk + i) * 16 + l15;      // im2col row 0..767
            uint32_t sw = ((hsel ^ ((q >> 2) & 1)) << 4);
            uint32_t A[4];
            LDSM4(A, ab0 + q * 32 + sw);
            DO4(d[i], A, bh1[0], bl1[0]);
            LDSM4(A, ab1 + q * 32 + sw);
            DO4(d[i], A, bh1[1], bl1[1]);
        }
        epi_store_h(smc, lane, base_blk, ox, oy, d);
    }
    __syncthreads();

    // ---- Stage D: conv2 via mma.sync (writes HH back) ----
    mma_layer<false>(smc, lane, wid, OFF_W2H, OFF_W2L, ox, oy, bz, out);
    __syncthreads();

    // ---- Stage E: conv3 via mma.sync + ReLU -> global ----
    mma_layer<true>(smc, lane, wid, OFF_W3H, OFF_W3L, ox, oy, bz, out);
}

extern "C" void kernel_launch(void* const* d_in, const int* in_sizes, int n_in,
                              void* d_out, int out_size) {
    const float* x  = (const float*)d_in[0];
    const float* w1 = (const float*)d_in[1];
    const float* w2 = (const float*)d_in[2];
    const float* w3 = (const float*)d_in[3];
    float* out = (float*)d_out;

    cudaFuncSetAttribute(net_fused_kernel,
                         cudaFuncAttributeMaxDynamicSharedMemorySize, SMEM_BYTES);

    dim3 grid(NTX, NTY, NB);
    net_fused_kernel<<<grid, NTHR, SMEM_BYTES>>>(x, w1, w2, w3, out);
}